// round 1
// baseline (speedup 1.0000x reference)
#include <cuda_runtime.h>
#include <cstdint>

#define HD 512
#define SEQT 4096
#define G3 1536
#define NCTA 128

// Scratch (static device allocations only — no cudaMalloc allowed)
__device__ float g_GI[2][SEQT][G3];      // precomputed input gates, ~50 MB
__device__ float g_h[2][2][HD];          // [phase][seq][H] double-buffered hidden
__device__ unsigned g_bar[SEQT];         // per-step arrival counters

__device__ __forceinline__ float sigf(float x) {
    return __fdividef(1.0f, 1.0f + __expf(-x));
}
__device__ __forceinline__ float tanh_fast(float x) {
    x = fminf(fmaxf(x, -30.0f), 30.0f);
    float e = __expf(2.0f * x);
    return __fdividef(e - 1.0f, e + 1.0f);
}

// ---------------------------------------------------------------------------
// Kernel 0: reset barrier counters and h buffers (must run every graph replay)
// ---------------------------------------------------------------------------
__global__ void init_kernel() {
    int i = blockIdx.x * blockDim.x + threadIdx.x;
    if (i < SEQT) g_bar[i] = 0u;
    if (i < 2 * 2 * HD) ((float*)g_h)[i] = 0.0f;
}

// ---------------------------------------------------------------------------
// Kernel 1: GI[s][t][:] = emb[tok] @ W_ih1^T + b_ih1   (8192x1536 = E @ W^T)
// 64x64x16 smem-tiled fp32 GEMM with embedding gather on the A side.
// ---------------------------------------------------------------------------
__global__ void __launch_bounds__(256) gi_gemm(const int* __restrict__ xs,
                                               const int* __restrict__ ys,
                                               const float* __restrict__ emb,
                                               const float* __restrict__ Wih,
                                               const float* __restrict__ bih) {
    __shared__ __align__(16) float As[16][64];
    __shared__ __align__(16) float Bs[16][64];

    const int tid  = threadIdx.x;
    const int col0 = blockIdx.x * 64;   // 24 tiles over 1536
    const int row0 = blockIdx.y * 64;   // 128 tiles over 8192
    const int tr = (tid >> 4) << 2;     // 0..60
    const int tc = (tid & 15) << 2;     // 0..60

    // cooperative load lane
    const int lr = tid >> 2;            // 0..63
    const int kv = (tid & 3) << 2;      // 0,4,8,12

    const int grow = row0 + lr;
    const int tok = (grow < SEQT) ? xs[grow] : ys[grow - SEQT];
    const float* arow = emb + (size_t)tok * HD;
    const float* brow = Wih + (size_t)(col0 + lr) * HD;

    float acc[4][4];
#pragma unroll
    for (int i = 0; i < 4; i++)
#pragma unroll
        for (int j = 0; j < 4; j++) acc[i][j] = 0.0f;

    for (int k0 = 0; k0 < HD; k0 += 16) {
        float4 a4 = *(const float4*)(arow + k0 + kv);
        float4 b4 = *(const float4*)(brow + k0 + kv);
        As[kv + 0][lr] = a4.x; As[kv + 1][lr] = a4.y;
        As[kv + 2][lr] = a4.z; As[kv + 3][lr] = a4.w;
        Bs[kv + 0][lr] = b4.x; Bs[kv + 1][lr] = b4.y;
        Bs[kv + 2][lr] = b4.z; Bs[kv + 3][lr] = b4.w;
        __syncthreads();
#pragma unroll
        for (int k = 0; k < 16; k++) {
            float4 av = *(const float4*)&As[k][tr];
            float4 bv = *(const float4*)&Bs[k][tc];
            acc[0][0] = fmaf(av.x, bv.x, acc[0][0]);
            acc[0][1] = fmaf(av.x, bv.y, acc[0][1]);
            acc[0][2] = fmaf(av.x, bv.z, acc[0][2]);
            acc[0][3] = fmaf(av.x, bv.w, acc[0][3]);
            acc[1][0] = fmaf(av.y, bv.x, acc[1][0]);
            acc[1][1] = fmaf(av.y, bv.y, acc[1][1]);
            acc[1][2] = fmaf(av.y, bv.z, acc[1][2]);
            acc[1][3] = fmaf(av.y, bv.w, acc[1][3]);
            acc[2][0] = fmaf(av.z, bv.x, acc[2][0]);
            acc[2][1] = fmaf(av.z, bv.y, acc[2][1]);
            acc[2][2] = fmaf(av.z, bv.z, acc[2][2]);
            acc[2][3] = fmaf(av.z, bv.w, acc[2][3]);
            acc[3][0] = fmaf(av.w, bv.x, acc[3][0]);
            acc[3][1] = fmaf(av.w, bv.y, acc[3][1]);
            acc[3][2] = fmaf(av.w, bv.z, acc[3][2]);
            acc[3][3] = fmaf(av.w, bv.w, acc[3][3]);
        }
        __syncthreads();
    }

    float4 bias = *(const float4*)(bih + col0 + tc);
#pragma unroll
    for (int ii = 0; ii < 4; ii++) {
        int gr = row0 + tr + ii;
        int s  = gr >> 12;
        int tt = gr & (SEQT - 1);
        float4 v;
        v.x = acc[ii][0] + bias.x;
        v.y = acc[ii][1] + bias.y;
        v.z = acc[ii][2] + bias.z;
        v.w = acc[ii][3] + bias.w;
        *(float4*)&g_GI[s][tt][col0 + tc] = v;
    }
}

// ---------------------------------------------------------------------------
// Kernel 2: persistent 4096-step GRU recurrence for both sequences.
// 128 CTAs x 192 threads. CTA b owns h indices [4b, 4b+4) -> 12 gate rows.
// Weights register-resident (32 floats/lane). Per-step global barrier.
// ---------------------------------------------------------------------------
__global__ void __launch_bounds__(192, 1) gru1_kernel(const float* __restrict__ Whh,
                                                      const float* __restrict__ bhh) {
    const int tid  = threadIdx.x;
    const int w    = tid >> 5;
    const int lane = tid & 31;
    const int bx   = blockIdx.x;

    __shared__ float sm_h[2][HD];
    __shared__ float sm_gh[2][12];

    // warp w owns local rows 2w, 2w+1 (of 12). lr -> global gate row.
    const int lr0 = 2 * w, lr1 = 2 * w + 1;
    const int row0 = (lr0 >> 2) * HD + bx * 4 + (lr0 & 3);
    const int row1 = (lr1 >> 2) * HD + bx * 4 + (lr1 & 3);

    float wa[16], wb[16];
#pragma unroll
    for (int j = 0; j < 16; j++) {
        wa[j] = Whh[(size_t)row0 * HD + lane + 32 * j];
        wb[j] = Whh[(size_t)row1 * HD + lane + 32 * j];
    }
    const float bh0 = bhh[row0];
    const float bh1 = bhh[row1];

    const int i4 = bx * 4 + tid;  // owned h index, valid for tid < 4

    for (int t = 0; t < SEQT; t++) {
        const int rd = t & 1, wr = rd ^ 1;

        // Prefetch input-gate values (GI is static w.r.t. the recurrence;
        // issue before the barrier wait so latency hides under the spin).
        float gr0, gz0, gn0, gr1, gz1, gn1;
        if (tid < 4) {
            const float* GI0 = &g_GI[0][t][0];
            const float* GI1 = &g_GI[1][t][0];
            gr0 = GI0[i4]; gz0 = GI0[HD + i4]; gn0 = GI0[2 * HD + i4];
            gr1 = GI1[i4]; gz1 = GI1[HD + i4]; gn1 = GI1[2 * HD + i4];
        }

        if (t > 0) {
            if (tid == 0) {
                volatile unsigned* p = &g_bar[t - 1];
                while (*p < (unsigned)NCTA) { }
                __threadfence();
            }
            __syncthreads();
        }

        // Stage h (both sequences) from L2 into smem once per CTA.
        if (tid < 128) {
            float4 v0 = __ldcg((const float4*)&g_h[rd][0][tid * 4]);
            float4 v1 = __ldcg((const float4*)&g_h[rd][1][tid * 4]);
            *(float4*)&sm_h[0][tid * 4] = v0;
            *(float4*)&sm_h[1][tid * 4] = v1;
        }
        __syncthreads();

        // Two rows x two sequences of 512-dot from register weights.
        float a00 = 0.f, a01 = 0.f, a10 = 0.f, a11 = 0.f;
#pragma unroll
        for (int j = 0; j < 16; j++) {
            float h0 = sm_h[0][lane + 32 * j];
            float h1 = sm_h[1][lane + 32 * j];
            a00 = fmaf(wa[j], h0, a00);
            a01 = fmaf(wa[j], h1, a01);
            a10 = fmaf(wb[j], h0, a10);
            a11 = fmaf(wb[j], h1, a11);
        }
#pragma unroll
        for (int o = 16; o; o >>= 1) {
            a00 += __shfl_xor_sync(0xffffffffu, a00, o);
            a01 += __shfl_xor_sync(0xffffffffu, a01, o);
            a10 += __shfl_xor_sync(0xffffffffu, a10, o);
            a11 += __shfl_xor_sync(0xffffffffu, a11, o);
        }
        if (lane == 0) {
            sm_gh[0][lr0] = a00 + bh0;
            sm_gh[1][lr0] = a01 + bh0;
            sm_gh[0][lr1] = a10 + bh1;
            sm_gh[1][lr1] = a11 + bh1;
        }
        __syncthreads();

        if (tid < 4) {
            {   // sequence x
                float r = sigf(gr0 + sm_gh[0][tid]);
                float z = sigf(gz0 + sm_gh[0][4 + tid]);
                float n = tanh_fast(gn0 + r * sm_gh[0][8 + tid]);
                float hold = sm_h[0][i4];
                g_h[wr][0][i4] = n + z * (hold - n);
            }
            {   // sequence y
                float r = sigf(gr1 + sm_gh[1][tid]);
                float z = sigf(gz1 + sm_gh[1][4 + tid]);
                float n = tanh_fast(gn1 + r * sm_gh[1][8 + tid]);
                float hold = sm_h[1][i4];
                g_h[wr][1][i4] = n + z * (hold - n);
            }
            __threadfence();
        }
        __syncthreads();
        if (tid == 0) atomicAdd(&g_bar[t], 1u);
    }
}

// ---------------------------------------------------------------------------
// Kernel 3: sentence GRU (2 steps) + MLP + log_softmax. Single CTA, tiny.
// Final token-GRU hiddens live in g_h[0][s][:] (4096 steps -> phase 0).
// ---------------------------------------------------------------------------
__global__ void __launch_bounds__(1024) tail_kernel(const float* __restrict__ Wih2,
                                                    const float* __restrict__ Whh2,
                                                    const float* __restrict__ bih2,
                                                    const float* __restrict__ bhh2,
                                                    const float* __restrict__ W1,
                                                    const float* __restrict__ b1,
                                                    const float* __restrict__ W2,
                                                    const float* __restrict__ b2,
                                                    float* __restrict__ out) {
    __shared__ float gi[G3], gh[G3], h1[HD], h2[HD], m1[128];
    const int tid = threadIdx.x, w = tid >> 5, lane = tid & 31;

    // step 1: input = hidden_x, h_prev = 0 (gh = b_hh2)
    for (int r = w; r < G3; r += 32) {
        float a = 0.f;
        for (int j = lane; j < HD; j += 32)
            a = fmaf(Wih2[(size_t)r * HD + j], g_h[0][0][j], a);
#pragma unroll
        for (int o = 16; o; o >>= 1) a += __shfl_xor_sync(0xffffffffu, a, o);
        if (lane == 0) gi[r] = a + bih2[r];
    }
    __syncthreads();
    if (tid < HD) {
        float r = sigf(gi[tid] + bhh2[tid]);
        float z = sigf(gi[HD + tid] + bhh2[HD + tid]);
        float n = tanh_fast(gi[2 * HD + tid] + r * bhh2[2 * HD + tid]);
        h1[tid] = (1.0f - z) * n;
    }
    __syncthreads();

    // step 2: input = hidden_y, h_prev = h1
    for (int r = w; r < G3; r += 32) {
        float a = 0.f, b = 0.f;
        for (int j = lane; j < HD; j += 32) {
            a = fmaf(Wih2[(size_t)r * HD + j], g_h[0][1][j], a);
            b = fmaf(Whh2[(size_t)r * HD + j], h1[j], b);
        }
#pragma unroll
        for (int o = 16; o; o >>= 1) {
            a += __shfl_xor_sync(0xffffffffu, a, o);
            b += __shfl_xor_sync(0xffffffffu, b, o);
        }
        if (lane == 0) { gi[r] = a + bih2[r]; gh[r] = b + bhh2[r]; }
    }
    __syncthreads();
    if (tid < HD) {
        float r = sigf(gi[tid] + gh[tid]);
        float z = sigf(gi[HD + tid] + gh[HD + tid]);
        float n = tanh_fast(gi[2 * HD + tid] + r * gh[2 * HD + tid]);
        h2[tid] = n + z * (h1[tid] - n);
    }
    __syncthreads();

    // MLP layer 1: relu(h2 @ W1^T + b1), 128 outputs
    for (int r = w; r < 128; r += 32) {
        float a = 0.f;
        for (int j = lane; j < HD; j += 32)
            a = fmaf(W1[(size_t)r * HD + j], h2[j], a);
#pragma unroll
        for (int o = 16; o; o >>= 1) a += __shfl_xor_sync(0xffffffffu, a, o);
        if (lane == 0) m1[r] = fmaxf(a + b1[r], 0.0f);
    }
    __syncthreads();

    // MLP layer 2 + log_softmax over 2 logits
    if (w == 0) {
        float a0 = 0.f, a1 = 0.f;
        for (int j = lane; j < 128; j += 32) {
            a0 = fmaf(W2[j], m1[j], a0);
            a1 = fmaf(W2[128 + j], m1[j], a1);
        }
#pragma unroll
        for (int o = 16; o; o >>= 1) {
            a0 += __shfl_xor_sync(0xffffffffu, a0, o);
            a1 += __shfl_xor_sync(0xffffffffu, a1, o);
        }
        if (lane == 0) {
            float v0 = fmaxf(a0 + b2[0], 0.0f);
            float v1 = fmaxf(a1 + b2[1], 0.0f);
            float m = fmaxf(v0, v1);
            float lse = m + logf(expf(v0 - m) + expf(v1 - m));
            out[0] = v0 - lse;
            out[1] = v1 - lse;
        }
    }
}

// ---------------------------------------------------------------------------
extern "C" void kernel_launch(void* const* d_in, const int* in_sizes, int n_in,
                              void* d_out, int out_size) {
    const int*   x    = (const int*)d_in[0];
    const int*   y    = (const int*)d_in[1];
    const float* emb  = (const float*)d_in[2];
    const float* Wih1 = (const float*)d_in[3];
    const float* Whh1 = (const float*)d_in[4];
    const float* bih1 = (const float*)d_in[5];
    const float* bhh1 = (const float*)d_in[6];
    const float* Wih2 = (const float*)d_in[7];
    const float* Whh2 = (const float*)d_in[8];
    const float* bih2 = (const float*)d_in[9];
    const float* bhh2 = (const float*)d_in[10];
    const float* W1   = (const float*)d_in[11];
    const float* b1   = (const float*)d_in[12];
    const float* W2   = (const float*)d_in[13];
    const float* b2   = (const float*)d_in[14];
    float* out = (float*)d_out;

    init_kernel<<<16, 256>>>();
    gi_gemm<<<dim3(24, 128), 256>>>(x, y, emb, Wih1, bih1);
    gru1_kernel<<<NCTA, 192>>>(Whh1, bhh1);
    tail_kernel<<<1, 1024>>>(Wih2, Whh2, bih2, bhh2, W1, b1, W2, b2, out);
}

// round 2
// speedup vs baseline: 1.2117x; 1.2117x over previous
#include <cuda_runtime.h>
#include <cstdint>

#define HD   512
#define SEQT 4096
#define G3   1536
#define REC_CTAS 32
#define GEMM_CTAS 116
#define NUNITS (GEMM_CTAS * 3)
#define NTILES (128 * 24)

// ---------------- static device scratch (no cudaMalloc allowed) -------------
__device__ __align__(16) float g_GI[2][SEQT][G3];          // precomputed input gates (~50MB)
__device__ unsigned long long g_htag[2][2][HD];            // {tag,val} packed, [buf][seq][i]
__device__ unsigned g_cnt[128];                            // per row-tile completion counters
__device__ float g_h1[HD], g_h2[HD];                       // sentence-GRU intermediates

// ---------------- memory-model helpers --------------------------------------
__device__ __forceinline__ unsigned ld_acq_u32(const unsigned* p) {
    unsigned v; asm volatile("ld.acquire.gpu.global.u32 %0,[%1];" : "=r"(v) : "l"(p)); return v;
}
__device__ __forceinline__ void red_rel_add(unsigned* p, unsigned v) {
    asm volatile("red.release.gpu.global.add.u32 [%0],%1;" :: "l"(p), "r"(v) : "memory");
}
__device__ __forceinline__ unsigned long long ld_rlx_u64(const unsigned long long* p) {
    unsigned long long v; asm volatile("ld.relaxed.gpu.global.b64 %0,[%1];" : "=l"(v) : "l"(p)); return v;
}
__device__ __forceinline__ void st_rlx_u64(unsigned long long* p, unsigned long long v) {
    asm volatile("st.relaxed.gpu.global.b64 [%0],%1;" :: "l"(p), "l"(v) : "memory");
}
__device__ __forceinline__ void fence_gpu() {
    asm volatile("fence.acq_rel.gpu;" ::: "memory");
}
__device__ __forceinline__ void bar_named(int id, int cnt) {
    asm volatile("bar.sync %0, %1;" :: "r"(id), "r"(cnt) : "memory");
}

__device__ __forceinline__ float sigf(float x) {
    return __fdividef(1.0f, 1.0f + __expf(-x));
}
__device__ __forceinline__ float tanh_fast(float x) {
    x = fminf(fmaxf(x, -30.0f), 30.0f);
    float e = __expf(2.0f * x);
    return __fdividef(e - 1.0f, e + 1.0f);
}
__device__ __forceinline__ float wredu(float v) {
#pragma unroll
    for (int o = 16; o; o >>= 1) v += __shfl_xor_sync(0xffffffffu, v, o);
    return v;
}

// ---------------------------------------------------------------------------
// Kernel 0: reset tags + GI counters (runs every graph replay)
// ---------------------------------------------------------------------------
__global__ void init_kernel() {
    int i = blockIdx.x * blockDim.x + threadIdx.x;
    if (i < 2 * 2 * HD) ((unsigned long long*)g_htag)[i] = 0ull;   // tag 0 never matches t>=1
    if (i < 128) g_cnt[i] = 0u;
}

// ---------------------------------------------------------------------------
// Fused kernel: 148 CTAs x 768 threads.
//   CTAs [0,32):   persistent GRU recurrence, 24 warps, each warp 2 gate rows
//                  x 2 sequences, weights register-resident. h exchanged via
//                  tag-embedded 8-byte words (no global barrier at all).
//   CTAs [32,148): 3 independent 256-thread GEMM units each; 64x64x16 tiled
//                  GEMM producing GI row-tile-ordered, interleaved x/y so
//                  early timesteps complete first. Completion advertised via
//                  per-row-tile release counters.
// ---------------------------------------------------------------------------
__global__ void __launch_bounds__(768, 1)
fused_kernel(const int* __restrict__ xs, const int* __restrict__ ys,
             const float* __restrict__ emb,
             const float* __restrict__ Wih, const float* __restrict__ bih,
             const float* __restrict__ Whh, const float* __restrict__ bhh) {
    const int tid = threadIdx.x;

    if (blockIdx.x >= REC_CTAS) {
        // ================== GEMM producer ==================
        __shared__ __align__(16) float pool[3 * 2048];   // per group: As[16*64] + Bs[16*64]
        const int gidx = tid >> 8;            // 0..2
        const int tidl = tid & 255;
        const int barid = gidx + 1;           // named barriers 1..3
        float* As = pool + gidx * 2048;
        float* Bs = As + 1024;

        const int tr = (tidl >> 4) << 2;
        const int tc = (tidl & 15) << 2;
        const int lr = tidl >> 2;
        const int kv = (tidl & 3) << 2;

        const int unit = (blockIdx.x - REC_CTAS) * 3 + gidx;

        for (int T = unit; T < NTILES; T += NUNITS) {
            const int e  = T / 24;
            const int c  = T - e * 24;
            const int xy = e & 1;
            const int trow = (e >> 1) << 6;
            const int col0 = c << 6;

            const int tok = (xy ? ys : xs)[trow + lr];
            const float* arow = emb + (size_t)tok * HD;
            const float* brow = Wih + (size_t)(col0 + lr) * HD;

            float acc[4][4];
#pragma unroll
            for (int i = 0; i < 4; i++)
#pragma unroll
                for (int j = 0; j < 4; j++) acc[i][j] = 0.0f;

            for (int k0 = 0; k0 < HD; k0 += 16) {
                float4 a4 = *(const float4*)(arow + k0 + kv);
                float4 b4 = *(const float4*)(brow + k0 + kv);
                As[(kv + 0) * 64 + lr] = a4.x; As[(kv + 1) * 64 + lr] = a4.y;
                As[(kv + 2) * 64 + lr] = a4.z; As[(kv + 3) * 64 + lr] = a4.w;
                Bs[(kv + 0) * 64 + lr] = b4.x; Bs[(kv + 1) * 64 + lr] = b4.y;
                Bs[(kv + 2) * 64 + lr] = b4.z; Bs[(kv + 3) * 64 + lr] = b4.w;
                bar_named(barid, 256);
#pragma unroll
                for (int k = 0; k < 16; k++) {
                    float4 av = *(const float4*)&As[k * 64 + tr];
                    float4 bv = *(const float4*)&Bs[k * 64 + tc];
                    acc[0][0] = fmaf(av.x, bv.x, acc[0][0]);
                    acc[0][1] = fmaf(av.x, bv.y, acc[0][1]);
                    acc[0][2] = fmaf(av.x, bv.z, acc[0][2]);
                    acc[0][3] = fmaf(av.x, bv.w, acc[0][3]);
                    acc[1][0] = fmaf(av.y, bv.x, acc[1][0]);
                    acc[1][1] = fmaf(av.y, bv.y, acc[1][1]);
                    acc[1][2] = fmaf(av.y, bv.z, acc[1][2]);
                    acc[1][3] = fmaf(av.y, bv.w, acc[1][3]);
                    acc[2][0] = fmaf(av.z, bv.x, acc[2][0]);
                    acc[2][1] = fmaf(av.z, bv.y, acc[2][1]);
                    acc[2][2] = fmaf(av.z, bv.z, acc[2][2]);
                    acc[2][3] = fmaf(av.z, bv.w, acc[2][3]);
                    acc[3][0] = fmaf(av.w, bv.x, acc[3][0]);
                    acc[3][1] = fmaf(av.w, bv.y, acc[3][1]);
                    acc[3][2] = fmaf(av.w, bv.z, acc[3][2]);
                    acc[3][3] = fmaf(av.w, bv.w, acc[3][3]);
                }
                bar_named(barid, 256);
            }

            float4 bias = *(const float4*)(bih + col0 + tc);
#pragma unroll
            for (int ii = 0; ii < 4; ii++) {
                float4 v;
                v.x = acc[ii][0] + bias.x;
                v.y = acc[ii][1] + bias.y;
                v.z = acc[ii][2] + bias.z;
                v.w = acc[ii][3] + bias.w;
                *(float4*)&g_GI[xy][trow + tr + ii][col0 + tc] = v;
            }
            bar_named(barid, 256);             // all stores ordered before counter
            if (tidl == 0) {
                fence_gpu();                   // cumulative: covers peers' stores
                red_rel_add(&g_cnt[e], 1u);
            }
        }
        return;
    }

    // ================== GRU recurrence ==================
    const int bx   = blockIdx.x;            // 0..31, owns h indices [16bx, 16bx+16)
    const int w    = tid >> 5;               // 24 warps
    const int lane = tid & 31;

    __shared__ float sm_h[2][HD];
    __shared__ float sm_gh[2][48];

    const int lr0 = 2 * w, lr1 = 2 * w + 1;                 // local rows 0..47
    const int g0 = ((lr0 >> 4) << 9) + (bx << 4) + (lr0 & 15);
    const int g1 = ((lr1 >> 4) << 9) + (bx << 4) + (lr1 & 15);

    float wa[16], wb[16];
#pragma unroll
    for (int j = 0; j < 16; j++) {
        wa[j] = Whh[(size_t)g0 * HD + lane + 32 * j];
        wb[j] = Whh[(size_t)g1 * HD + lane + 32 * j];
    }
    const float bh0 = bhh[g0];
    const float bh1 = bhh[g1];
    const int i4 = (bx << 4) + tid;          // owned h index (tid < 16)

    for (int t = 0; t < SEQT; t++) {
        // ---- GI readiness (once per 64-step row tile; monotonic) ----
        if ((t & 63) == 0) {
            if (tid == 0) {
                const int ex = (t >> 6) << 1;
                while (ld_acq_u32(&g_cnt[ex])     < 24u) { }
                while (ld_acq_u32(&g_cnt[ex + 1]) < 24u) { }
            }
            __syncthreads();
        }

        // ---- GI prefetch (latency hides under the h poll) ----
        float gr0, gz0, gn0, gr1, gz1, gn1;
        if (tid < 16) {
            const float* GI0 = &g_GI[0][t][0];
            const float* GI1 = &g_GI[1][t][0];
            gr0 = GI0[i4]; gz0 = GI0[512 + i4]; gn0 = GI0[1024 + i4];
            gr1 = GI1[i4]; gz1 = GI1[512 + i4]; gn1 = GI1[1024 + i4];
        }

        // ---- stage h: poll tag-embedded words (parallel across 512 threads) ----
        if (tid < HD) {
            if (t == 0) {
                sm_h[0][tid] = 0.0f;
                sm_h[1][tid] = 0.0f;
            } else {
                const int buf = t & 1;
                unsigned long long a;
                do { a = ld_rlx_u64(&g_htag[buf][0][tid]); } while ((unsigned)(a >> 32) != (unsigned)t);
                sm_h[0][tid] = __uint_as_float((unsigned)a);
                do { a = ld_rlx_u64(&g_htag[buf][1][tid]); } while ((unsigned)(a >> 32) != (unsigned)t);
                sm_h[1][tid] = __uint_as_float((unsigned)a);
            }
        }
        __syncthreads();

        // ---- 2 gate rows x 2 sequences per warp, register weights ----
        float a00 = 0.f, a01 = 0.f, a10 = 0.f, a11 = 0.f;
#pragma unroll
        for (int j = 0; j < 16; j++) {
            float h0 = sm_h[0][lane + 32 * j];
            float h1 = sm_h[1][lane + 32 * j];
            a00 = fmaf(wa[j], h0, a00);
            a01 = fmaf(wa[j], h1, a01);
            a10 = fmaf(wb[j], h0, a10);
            a11 = fmaf(wb[j], h1, a11);
        }
#pragma unroll
        for (int o = 16; o; o >>= 1) {
            a00 += __shfl_xor_sync(0xffffffffu, a00, o);
            a01 += __shfl_xor_sync(0xffffffffu, a01, o);
            a10 += __shfl_xor_sync(0xffffffffu, a10, o);
            a11 += __shfl_xor_sync(0xffffffffu, a11, o);
        }
        if (lane == 0) {
            sm_gh[0][lr0] = a00 + bh0;
            sm_gh[1][lr0] = a01 + bh0;
            sm_gh[0][lr1] = a10 + bh1;
            sm_gh[1][lr1] = a11 + bh1;
        }
        __syncthreads();

        // ---- gate + publish (tag carries the data dependency; no fence) ----
        if (tid < 16) {
            const unsigned long long tagv = ((unsigned long long)(unsigned)(t + 1)) << 32;
            {
                float r = sigf(gr0 + sm_gh[0][tid]);
                float z = sigf(gz0 + sm_gh[0][16 + tid]);
                float n = tanh_fast(gn0 + r * sm_gh[0][32 + tid]);
                float hn = n + z * (sm_h[0][i4] - n);
                st_rlx_u64(&g_htag[(t + 1) & 1][0][i4],
                           tagv | (unsigned long long)__float_as_uint(hn));
            }
            {
                float r = sigf(gr1 + sm_gh[1][tid]);
                float z = sigf(gz1 + sm_gh[1][16 + tid]);
                float n = tanh_fast(gn1 + r * sm_gh[1][32 + tid]);
                float hn = n + z * (sm_h[1][i4] - n);
                st_rlx_u64(&g_htag[(t + 1) & 1][1][i4],
                           tagv | (unsigned long long)__float_as_uint(hn));
            }
        }
        // No extra barrier: stagers can only overwrite sm_h after observing
        // ALL tags for t+1, which data-depend on this step's sm_h/sm_gh reads.
    }
}

// ---------------------------------------------------------------------------
// Tail A: sentence-GRU step 1 (h_prev = 0). 16 CTAs x 256. Warp owns 4 h.
// Final token-GRU hiddens: g_htag[0][seq][i] (tag 4096), value in low bits.
// ---------------------------------------------------------------------------
__global__ void __launch_bounds__(256) tailA(const float* __restrict__ Wih2,
                                             const float* __restrict__ bih2,
                                             const float* __restrict__ bhh2) {
    __shared__ float sx[HD];
    const int tid = threadIdx.x, w = tid >> 5, lane = tid & 31;
    for (int i = tid; i < HD; i += 256)
        sx[i] = __uint_as_float((unsigned)g_htag[0][0][i]);
    __syncthreads();

    const int i0 = blockIdx.x * 32 + w * 4;
    float acc[4][3];
#pragma unroll
    for (int q = 0; q < 4; q++)
#pragma unroll
        for (int g = 0; g < 3; g++) acc[q][g] = 0.0f;

    for (int k = 0; k < 16; k++) {
        int j = lane + 32 * k;
        float h = sx[j];
#pragma unroll
        for (int q = 0; q < 4; q++)
#pragma unroll
            for (int g = 0; g < 3; g++)
                acc[q][g] = fmaf(Wih2[(size_t)(g * 512 + i0 + q) * HD + j], h, acc[q][g]);
    }
#pragma unroll
    for (int q = 0; q < 4; q++)
#pragma unroll
        for (int g = 0; g < 3; g++) acc[q][g] = wredu(acc[q][g]);

    if (lane == 0) {
#pragma unroll
        for (int q = 0; q < 4; q++) {
            int i = i0 + q;
            float r = sigf(acc[q][0] + bih2[i] + bhh2[i]);
            float z = sigf(acc[q][1] + bih2[512 + i] + bhh2[512 + i]);
            float n = tanh_fast(acc[q][2] + bih2[1024 + i] + r * bhh2[1024 + i]);
            g_h1[i] = (1.0f - z) * n;
        }
    }
}

// ---------------------------------------------------------------------------
// Tail B: sentence-GRU step 2 (input hy, h_prev = h1). 16 CTAs x 512.
// Warp owns 2 h -> 6 dots each.
// ---------------------------------------------------------------------------
__global__ void __launch_bounds__(512) tailB(const float* __restrict__ Wih2,
                                             const float* __restrict__ Whh2,
                                             const float* __restrict__ bih2,
                                             const float* __restrict__ bhh2) {
    __shared__ float sy[HD], s1[HD];
    const int tid = threadIdx.x, w = tid >> 5, lane = tid & 31;
    for (int i = tid; i < HD; i += 512) {
        sy[i] = __uint_as_float((unsigned)g_htag[0][1][i]);
        s1[i] = g_h1[i];
    }
    __syncthreads();

    const int i0 = blockIdx.x * 32 + w * 2;
    float acc[2][6];
#pragma unroll
    for (int q = 0; q < 2; q++)
#pragma unroll
        for (int g = 0; g < 6; g++) acc[q][g] = 0.0f;

    for (int k = 0; k < 16; k++) {
        int j = lane + 32 * k;
        float hy = sy[j], h1 = s1[j];
#pragma unroll
        for (int q = 0; q < 2; q++) {
#pragma unroll
            for (int g = 0; g < 3; g++) {
                size_t row = (size_t)(g * 512 + i0 + q) * HD + j;
                acc[q][g]     = fmaf(Wih2[row], hy, acc[q][g]);
                acc[q][g + 3] = fmaf(Whh2[row], h1, acc[q][g + 3]);
            }
        }
    }
#pragma unroll
    for (int q = 0; q < 2; q++)
#pragma unroll
        for (int g = 0; g < 6; g++) acc[q][g] = wredu(acc[q][g]);

    if (lane == 0) {
#pragma unroll
        for (int q = 0; q < 2; q++) {
            int i = i0 + q;
            float r = sigf(acc[q][0] + bih2[i] + acc[q][3] + bhh2[i]);
            float z = sigf(acc[q][1] + bih2[512 + i] + acc[q][4] + bhh2[512 + i]);
            float n = tanh_fast(acc[q][2] + bih2[1024 + i] + r * (acc[q][5] + bhh2[1024 + i]));
            g_h2[i] = n + z * (s1[i] - n);
        }
    }
}

// ---------------------------------------------------------------------------
// Tail C: MLP + log_softmax. 1 CTA x 1024 (data now hot in L2).
// ---------------------------------------------------------------------------
__global__ void __launch_bounds__(1024) tailC(const float* __restrict__ W1,
                                              const float* __restrict__ b1,
                                              const float* __restrict__ W2,
                                              const float* __restrict__ b2,
                                              float* __restrict__ out) {
    __shared__ float s2[HD], m1[128];
    const int tid = threadIdx.x, w = tid >> 5, lane = tid & 31;
    if (tid < HD) s2[tid] = g_h2[tid];
    __syncthreads();

    const int r0 = w * 4;
    float acc[4] = {0.f, 0.f, 0.f, 0.f};
    for (int k = 0; k < 16; k++) {
        int j = lane + 32 * k;
        float h = s2[j];
#pragma unroll
        for (int q = 0; q < 4; q++)
            acc[q] = fmaf(W1[(size_t)(r0 + q) * HD + j], h, acc[q]);
    }
#pragma unroll
    for (int q = 0; q < 4; q++) acc[q] = wredu(acc[q]);
    if (lane == 0) {
#pragma unroll
        for (int q = 0; q < 4; q++)
            m1[r0 + q] = fmaxf(acc[q] + b1[r0 + q], 0.0f);
    }
    __syncthreads();

    if (w == 0) {
        float a0 = 0.f, a1 = 0.f;
        for (int k = 0; k < 4; k++) {
            int j = lane + 32 * k;
            a0 = fmaf(W2[j], m1[j], a0);
            a1 = fmaf(W2[128 + j], m1[j], a1);
        }
        a0 = wredu(a0);
        a1 = wredu(a1);
        if (lane == 0) {
            float v0 = fmaxf(a0 + b2[0], 0.0f);
            float v1 = fmaxf(a1 + b2[1], 0.0f);
            float m = fmaxf(v0, v1);
            float lse = m + logf(expf(v0 - m) + expf(v1 - m));
            out[0] = v0 - lse;
            out[1] = v1 - lse;
        }
    }
}

// ---------------------------------------------------------------------------
extern "C" void kernel_launch(void* const* d_in, const int* in_sizes, int n_in,
                              void* d_out, int out_size) {
    const int*   x    = (const int*)d_in[0];
    const int*   y    = (const int*)d_in[1];
    const float* emb  = (const float*)d_in[2];
    const float* Wih1 = (const float*)d_in[3];
    const float* Whh1 = (const float*)d_in[4];
    const float* bih1 = (const float*)d_in[5];
    const float* bhh1 = (const float*)d_in[6];
    const float* Wih2 = (const float*)d_in[7];
    const float* Whh2 = (const float*)d_in[8];
    const float* bih2 = (const float*)d_in[9];
    const float* bhh2 = (const float*)d_in[10];
    const float* W1   = (const float*)d_in[11];
    const float* b1   = (const float*)d_in[12];
    const float* W2   = (const float*)d_in[13];
    const float* b2   = (const float*)d_in[14];
    float* out = (float*)d_out;

    init_kernel<<<2, 1024>>>();
    fused_kernel<<<REC_CTAS + GEMM_CTAS, 768>>>(x, y, emb, Wih1, bih1, Whh1, bhh1);
    tailA<<<16, 256>>>(Wih2, bih2, bhh2);
    tailB<<<16, 512>>>(Wih2, Whh2, bih2, bhh2);
    tailC<<<1, 1024>>>(W1, b1, W2, b2, out);
}

// round 3
// speedup vs baseline: 1.8571x; 1.5327x over previous
#include <cuda_runtime.h>
#include <cstdint>

#define HD   512
#define SEQT 4096
#define G3   1536
#define REC_CTAS 64            // 32 per sequence
#define GEMM_CTAS 84
#define NUNITS (GEMM_CTAS * 3)
#define NTILES (128 * 24)

// ---------------- static device scratch (no cudaMalloc allowed) -------------
__device__ __align__(16) float g_GI[2][SEQT][G3];          // precomputed input gates (~50MB)
__device__ unsigned long long g_htag[2][2][HD];            // {tag,val}, [buf][seq][i]
__device__ unsigned g_cnt[128];                            // per row-tile completion counters
__device__ float g_h1[HD], g_h2[HD];                       // sentence-GRU intermediates
__device__ float g_sink;                                   // prefetch sink (never read)

// ---------------- memory-model helpers --------------------------------------
__device__ __forceinline__ unsigned ld_acq_u32(const unsigned* p) {
    unsigned v; asm volatile("ld.acquire.gpu.global.u32 %0,[%1];" : "=r"(v) : "l"(p)); return v;
}
__device__ __forceinline__ void red_rel_add(unsigned* p, unsigned v) {
    asm volatile("red.release.gpu.global.add.u32 [%0],%1;" :: "l"(p), "r"(v) : "memory");
}
__device__ __forceinline__ unsigned long long ld_rlx_u64(const unsigned long long* p) {
    unsigned long long v; asm volatile("ld.relaxed.gpu.global.b64 %0,[%1];" : "=l"(v) : "l"(p)); return v;
}
__device__ __forceinline__ void st_rlx_u64(unsigned long long* p, unsigned long long v) {
    asm volatile("st.relaxed.gpu.global.b64 [%0],%1;" :: "l"(p), "l"(v) : "memory");
}
__device__ __forceinline__ void fence_gpu() {
    asm volatile("fence.acq_rel.gpu;" ::: "memory");
}
__device__ __forceinline__ void bar_named(int id, int cnt) {
    asm volatile("bar.sync %0, %1;" :: "r"(id), "r"(cnt) : "memory");
}

__device__ __forceinline__ float sigf(float x) {
    return __fdividef(1.0f, 1.0f + __expf(-x));
}
__device__ __forceinline__ float tanh_fast(float x) {
    x = fminf(fmaxf(x, -30.0f), 30.0f);
    float e = __expf(2.0f * x);
    return __fdividef(e - 1.0f, e + 1.0f);
}
__device__ __forceinline__ float wredu(float v) {
#pragma unroll
    for (int o = 16; o; o >>= 1) v += __shfl_xor_sync(0xffffffffu, v, o);
    return v;
}

// ---------------------------------------------------------------------------
// Kernel 0: reset tags + GI counters (runs every graph replay)
// ---------------------------------------------------------------------------
__global__ void init_kernel() {
    int i = blockIdx.x * blockDim.x + threadIdx.x;
    if (i < 2 * 2 * HD) ((unsigned long long*)g_htag)[i] = 0ull;   // tag 0 never matches t>=1
    if (i < 128) g_cnt[i] = 0u;
}

// ---------------------------------------------------------------------------
// Fused kernel: 148 CTAs x 768 threads.
//   CTAs [0,64):   persistent GRU recurrence, split by sequence:
//                  seq = bx>>5, c = bx&31 owns h indices [16c,16c+16).
//                  24 warps x 2 gate rows each; weights register-resident.
//                  h all-gathered via tag-embedded 8-byte words: exactly ONE
//                  polled word per thread per step. No global barrier.
//   CTAs [64,148): 3 x 256-thread GEMM units each, producing GI row-tiles.
//                  After GI done, prefetch tail weights into L2.
// ---------------------------------------------------------------------------
__global__ void __launch_bounds__(768, 1)
fused_kernel(const int* __restrict__ xs, const int* __restrict__ ys,
             const float* __restrict__ emb,
             const float* __restrict__ Wih, const float* __restrict__ bih,
             const float* __restrict__ Whh, const float* __restrict__ bhh,
             const float* __restrict__ Wih2, const float* __restrict__ Whh2,
             const float* __restrict__ W1) {
    const int tid = threadIdx.x;

    if (blockIdx.x >= REC_CTAS) {
        // ================== GEMM producer ==================
        __shared__ __align__(16) float pool[3 * 2048];
        const int gidx = tid >> 8;            // 0..2
        const int tidl = tid & 255;
        const int barid = gidx + 1;           // named barriers 1..3
        float* As = pool + gidx * 2048;
        float* Bs = As + 1024;

        const int tr = (tidl >> 4) << 2;
        const int tc = (tidl & 15) << 2;
        const int lr = tidl >> 2;
        const int kv = (tidl & 3) << 2;

        const int unit = (blockIdx.x - REC_CTAS) * 3 + gidx;

        for (int T = unit; T < NTILES; T += NUNITS) {
            const int e  = T / 24;
            const int c  = T - e * 24;
            const int xy = e & 1;
            const int trow = (e >> 1) << 6;
            const int col0 = c << 6;

            const int tok = (xy ? ys : xs)[trow + lr];
            const float* arow = emb + (size_t)tok * HD;
            const float* brow = Wih + (size_t)(col0 + lr) * HD;

            float acc[4][4];
#pragma unroll
            for (int i = 0; i < 4; i++)
#pragma unroll
                for (int j = 0; j < 4; j++) acc[i][j] = 0.0f;

            for (int k0 = 0; k0 < HD; k0 += 16) {
                float4 a4 = *(const float4*)(arow + k0 + kv);
                float4 b4 = *(const float4*)(brow + k0 + kv);
                As[(kv + 0) * 64 + lr] = a4.x; As[(kv + 1) * 64 + lr] = a4.y;
                As[(kv + 2) * 64 + lr] = a4.z; As[(kv + 3) * 64 + lr] = a4.w;
                Bs[(kv + 0) * 64 + lr] = b4.x; Bs[(kv + 1) * 64 + lr] = b4.y;
                Bs[(kv + 2) * 64 + lr] = b4.z; Bs[(kv + 3) * 64 + lr] = b4.w;
                bar_named(barid, 256);
#pragma unroll
                for (int k = 0; k < 16; k++) {
                    float4 av = *(const float4*)&As[k * 64 + tr];
                    float4 bv = *(const float4*)&Bs[k * 64 + tc];
                    acc[0][0] = fmaf(av.x, bv.x, acc[0][0]);
                    acc[0][1] = fmaf(av.x, bv.y, acc[0][1]);
                    acc[0][2] = fmaf(av.x, bv.z, acc[0][2]);
                    acc[0][3] = fmaf(av.x, bv.w, acc[0][3]);
                    acc[1][0] = fmaf(av.y, bv.x, acc[1][0]);
                    acc[1][1] = fmaf(av.y, bv.y, acc[1][1]);
                    acc[1][2] = fmaf(av.y, bv.z, acc[1][2]);
                    acc[1][3] = fmaf(av.y, bv.w, acc[1][3]);
                    acc[2][0] = fmaf(av.z, bv.x, acc[2][0]);
                    acc[2][1] = fmaf(av.z, bv.y, acc[2][1]);
                    acc[2][2] = fmaf(av.z, bv.z, acc[2][2]);
                    acc[2][3] = fmaf(av.z, bv.w, acc[2][3]);
                    acc[3][0] = fmaf(av.w, bv.x, acc[3][0]);
                    acc[3][1] = fmaf(av.w, bv.y, acc[3][1]);
                    acc[3][2] = fmaf(av.w, bv.z, acc[3][2]);
                    acc[3][3] = fmaf(av.w, bv.w, acc[3][3]);
                }
                bar_named(barid, 256);
            }

            float4 bias = *(const float4*)(bih + col0 + tc);
#pragma unroll
            for (int ii = 0; ii < 4; ii++) {
                float4 v;
                v.x = acc[ii][0] + bias.x;
                v.y = acc[ii][1] + bias.y;
                v.z = acc[ii][2] + bias.z;
                v.w = acc[ii][3] + bias.w;
                *(float4*)&g_GI[xy][trow + tr + ii][col0 + tc] = v;
            }
            bar_named(barid, 256);
            if (tidl == 0) {
                fence_gpu();
                red_rel_add(&g_cnt[e], 1u);
            }
        }

        // ---- warm L2 with tail weights (tails would otherwise be DRAM-bound)
        {
            const int nthr = GEMM_CTAS * 768;
            const int gt = (blockIdx.x - REC_CTAS) * 768 + tid;
            float s = 0.0f;
            const int n4 = (G3 * HD) / 4;          // 196608 float4 per matrix
            for (int i = gt; i < n4; i += nthr) {
                float4 a = __ldcg((const float4*)Wih2 + i);
                float4 b = __ldcg((const float4*)Whh2 + i);
                s += a.x + a.w + b.x + b.w;
            }
            const int m4 = (128 * HD) / 4;
            for (int i = gt; i < m4; i += nthr) {
                float4 a = __ldcg((const float4*)W1 + i);
                s += a.x + a.w;
            }
            if (s == 1.2345678e38f) g_sink = s;    // never true; defeats DCE
        }
        return;
    }

    // ================== GRU recurrence (one sequence per CTA group) =========
    const int seq = blockIdx.x >> 5;          // 0 = x, 1 = y
    const int c   = blockIdx.x & 31;          // owns h indices [16c, 16c+16)
    const int w    = tid >> 5;                // 24 warps
    const int lane = tid & 31;

    __shared__ float sm_h[HD];
    __shared__ float sm_gh[48];

    const int lr0 = 2 * w, lr1 = 2 * w + 1;   // local rows 0..47 (gate-major)
    const int g0 = ((lr0 >> 4) << 9) + (c << 4) + (lr0 & 15);
    const int g1 = ((lr1 >> 4) << 9) + (c << 4) + (lr1 & 15);

    float wa[16], wb[16];
#pragma unroll
    for (int j = 0; j < 16; j++) {
        wa[j] = Whh[(size_t)g0 * HD + lane + 32 * j];
        wb[j] = Whh[(size_t)g1 * HD + lane + 32 * j];
    }
    const float bh0 = bhh[g0];
    const float bh1 = bhh[g1];
    const int i16 = (c << 4) + tid;           // owned h index (tid < 16)

    for (int t = 0; t < SEQT; t++) {
        // ---- GI readiness (one counter for this seq, every 64 steps) ----
        if ((t & 63) == 0) {
            if (tid == 0) {
                const int e = ((t >> 6) << 1) + seq;
                while (ld_acq_u32(&g_cnt[e]) < 24u) { }
            }
            __syncthreads();
        }

        // ---- GI prefetch (latency hides under the h poll) ----
        float gr, gz, gn;
        if (tid < 16) {
            const float* GI = &g_GI[seq][t][0];
            gr = GI[i16]; gz = GI[512 + i16]; gn = GI[1024 + i16];
        }

        // ---- stage h: exactly one tag-embedded word per thread ----
        if (tid < HD) {
            float hv;
            if (t == 0) {
                hv = 0.0f;
            } else {
                const unsigned long long* p = &g_htag[t & 1][seq][tid];
                unsigned long long a = ld_rlx_u64(p);
                while ((unsigned)(a >> 32) != (unsigned)t) a = ld_rlx_u64(p);
                hv = __uint_as_float((unsigned)a);
            }
            sm_h[tid] = hv;
        }
        __syncthreads();

        // ---- 2 gate rows per warp, register weights ----
        float a0 = 0.f, a1 = 0.f;
#pragma unroll
        for (int j = 0; j < 16; j++) {
            float h = sm_h[lane + 32 * j];
            a0 = fmaf(wa[j], h, a0);
            a1 = fmaf(wb[j], h, a1);
        }
#pragma unroll
        for (int o = 16; o; o >>= 1) {
            a0 += __shfl_xor_sync(0xffffffffu, a0, o);
            a1 += __shfl_xor_sync(0xffffffffu, a1, o);
        }
        if (lane == 0) {
            sm_gh[lr0] = a0 + bh0;
            sm_gh[lr1] = a1 + bh1;
        }
        __syncthreads();

        // ---- gate + publish (tag carries the dependency; no fence) ----
        if (tid < 16) {
            float r = sigf(gr + sm_gh[tid]);
            float z = sigf(gz + sm_gh[16 + tid]);
            float n = tanh_fast(gn + r * sm_gh[32 + tid]);
            float hn = n + z * (sm_h[i16] - n);
            st_rlx_u64(&g_htag[(t + 1) & 1][seq][i16],
                       (((unsigned long long)(unsigned)(t + 1)) << 32) |
                       (unsigned long long)__float_as_uint(hn));
        }
        // No trailing barrier needed: a word for step t+2 can only be written
        // after its owner observed ALL tags of t+1, which requires every CTA
        // (including this one) to have finished reading step t's words.
    }
}

// ---------------------------------------------------------------------------
// Tail A: sentence-GRU step 1 (input hidden_x, h_prev = 0). 128 CTAs x 128.
// Warp handles one h index (3 gate-row dots).
// ---------------------------------------------------------------------------
__global__ void __launch_bounds__(128) tailA(const float* __restrict__ Wih2,
                                             const float* __restrict__ bih2,
                                             const float* __restrict__ bhh2) {
    __shared__ float sx[HD];
    const int tid = threadIdx.x, w = tid >> 5, lane = tid & 31;
    for (int i = tid; i < HD; i += 128)
        sx[i] = __uint_as_float((unsigned)g_htag[0][0][i]);
    __syncthreads();

    const int i = blockIdx.x * 4 + w;
    float ar = 0.f, az = 0.f, an = 0.f;
    for (int k = 0; k < 16; k++) {
        int j = lane + 32 * k;
        float h = sx[j];
        ar = fmaf(Wih2[(size_t)i * HD + j], h, ar);
        az = fmaf(Wih2[(size_t)(512 + i) * HD + j], h, az);
        an = fmaf(Wih2[(size_t)(1024 + i) * HD + j], h, an);
    }
    ar = wredu(ar); az = wredu(az); an = wredu(an);
    if (lane == 0) {
        float r = sigf(ar + bih2[i] + bhh2[i]);
        float z = sigf(az + bih2[512 + i] + bhh2[512 + i]);
        float n = tanh_fast(an + bih2[1024 + i] + r * bhh2[1024 + i]);
        g_h1[i] = (1.0f - z) * n;
    }
}

// ---------------------------------------------------------------------------
// Tail B: sentence-GRU step 2 (input hidden_y, h_prev = h1). 128 CTAs x 128.
// ---------------------------------------------------------------------------
__global__ void __launch_bounds__(128) tailB(const float* __restrict__ Wih2,
                                             const float* __restrict__ Whh2,
                                             const float* __restrict__ bih2,
                                             const float* __restrict__ bhh2) {
    __shared__ float sy[HD], s1[HD];
    const int tid = threadIdx.x, w = tid >> 5, lane = tid & 31;
    for (int i = tid; i < HD; i += 128) {
        sy[i] = __uint_as_float((unsigned)g_htag[0][1][i]);
        s1[i] = g_h1[i];
    }
    __syncthreads();

    const int i = blockIdx.x * 4 + w;
    float ir = 0.f, iz = 0.f, in_ = 0.f, hr = 0.f, hz = 0.f, hn_ = 0.f;
    for (int k = 0; k < 16; k++) {
        int j = lane + 32 * k;
        float hy = sy[j], h1 = s1[j];
        size_t r0 = (size_t)i * HD + j;
        size_t r1 = (size_t)(512 + i) * HD + j;
        size_t r2 = (size_t)(1024 + i) * HD + j;
        ir = fmaf(Wih2[r0], hy, ir);   hr = fmaf(Whh2[r0], h1, hr);
        iz = fmaf(Wih2[r1], hy, iz);   hz = fmaf(Whh2[r1], h1, hz);
        in_ = fmaf(Wih2[r2], hy, in_); hn_ = fmaf(Whh2[r2], h1, hn_);
    }
    ir = wredu(ir); iz = wredu(iz); in_ = wredu(in_);
    hr = wredu(hr); hz = wredu(hz); hn_ = wredu(hn_);
    if (lane == 0) {
        float r = sigf(ir + bih2[i] + hr + bhh2[i]);
        float z = sigf(iz + bih2[512 + i] + hz + bhh2[512 + i]);
        float n = tanh_fast(in_ + bih2[1024 + i] + r * (hn_ + bhh2[1024 + i]));
        g_h2[i] = n + z * (s1[i] - n);
    }
}

// ---------------------------------------------------------------------------
// Tail C: MLP + log_softmax. 1 CTA x 1024.
// ---------------------------------------------------------------------------
__global__ void __launch_bounds__(1024) tailC(const float* __restrict__ W1,
                                              const float* __restrict__ b1,
                                              const float* __restrict__ W2,
                                              const float* __restrict__ b2,
                                              float* __restrict__ out) {
    __shared__ float s2[HD], m1[128];
    const int tid = threadIdx.x, w = tid >> 5, lane = tid & 31;
    if (tid < HD) s2[tid] = g_h2[tid];
    __syncthreads();

    const int r0 = w * 4;
    float acc[4] = {0.f, 0.f, 0.f, 0.f};
    for (int k = 0; k < 16; k++) {
        int j = lane + 32 * k;
        float h = s2[j];
#pragma unroll
        for (int q = 0; q < 4; q++)
            acc[q] = fmaf(W1[(size_t)(r0 + q) * HD + j], h, acc[q]);
    }
#pragma unroll
    for (int q = 0; q < 4; q++) acc[q] = wredu(acc[q]);
    if (lane == 0) {
#pragma unroll
        for (int q = 0; q < 4; q++)
            m1[r0 + q] = fmaxf(acc[q] + b1[r0 + q], 0.0f);
    }
    __syncthreads();

    if (w == 0) {
        float a0 = 0.f, a1 = 0.f;
        for (int k = 0; k < 4; k++) {
            int j = lane + 32 * k;
            a0 = fmaf(W2[j], m1[j], a0);
            a1 = fmaf(W2[128 + j], m1[j], a1);
        }
        a0 = wredu(a0);
        a1 = wredu(a1);
        if (lane == 0) {
            float v0 = fmaxf(a0 + b2[0], 0.0f);
            float v1 = fmaxf(a1 + b2[1], 0.0f);
            float m = fmaxf(v0, v1);
            float lse = m + logf(expf(v0 - m) + expf(v1 - m));
            out[0] = v0 - lse;
            out[1] = v1 - lse;
        }
    }
}

// ---------------------------------------------------------------------------
extern "C" void kernel_launch(void* const* d_in, const int* in_sizes, int n_in,
                              void* d_out, int out_size) {
    const int*   x    = (const int*)d_in[0];
    const int*   y    = (const int*)d_in[1];
    const float* emb  = (const float*)d_in[2];
    const float* Wih1 = (const float*)d_in[3];
    const float* Whh1 = (const float*)d_in[4];
    const float* bih1 = (const float*)d_in[5];
    const float* bhh1 = (const float*)d_in[6];
    const float* Wih2 = (const float*)d_in[7];
    const float* Whh2 = (const float*)d_in[8];
    const float* bih2 = (const float*)d_in[9];
    const float* bhh2 = (const float*)d_in[10];
    const float* W1   = (const float*)d_in[11];
    const float* b1   = (const float*)d_in[12];
    const float* W2   = (const float*)d_in[13];
    const float* b2   = (const float*)d_in[14];
    float* out = (float*)d_out;

    init_kernel<<<2, 1024>>>();
    fused_kernel<<<REC_CTAS + GEMM_CTAS, 768>>>(x, y, emb, Wih1, bih1, Whh1, bhh1,
                                                Wih2, Whh2, W1);
    tailA<<<128, 128>>>(Wih2, bih2, bhh2);
    tailB<<<128, 128>>>(Wih2, Whh2, bih2, bhh2);
    tailC<<<1, 1024>>>(W1, b1, W2, b2, out);
}

// round 4
// speedup vs baseline: 2.1055x; 1.1337x over previous
#include <cuda_runtime.h>
#include <cstdint>

#define HD   512
#define SEQT 4096
#define G3   1536
#define REC_CTAS 128           // 64 per sequence
#define GEMM_CTAS 20
#define NUNITS (GEMM_CTAS * 3)
#define NTILES (128 * 24)

// ---------------- static device scratch (no cudaMalloc allowed) -------------
__device__ __align__(16) float g_GI[2][SEQT][G3];          // precomputed input gates (~50MB)
__device__ unsigned long long g_htag[2][2][HD];            // {tag,val}, [buf][seq][i]
__device__ unsigned g_cnt[128];                            // per row-tile completion counters
__device__ float g_h1[HD], g_h2[HD];                       // sentence-GRU intermediates
__device__ float g_sink;                                   // prefetch sink (never read)

// ---------------- memory-model helpers --------------------------------------
__device__ __forceinline__ unsigned ld_acq_u32(const unsigned* p) {
    unsigned v; asm volatile("ld.acquire.gpu.global.u32 %0,[%1];" : "=r"(v) : "l"(p)); return v;
}
__device__ __forceinline__ void red_rel_add(unsigned* p, unsigned v) {
    asm volatile("red.release.gpu.global.add.u32 [%0],%1;" :: "l"(p), "r"(v) : "memory");
}
__device__ __forceinline__ unsigned long long ld_rlx_u64(const unsigned long long* p) {
    unsigned long long v; asm volatile("ld.relaxed.gpu.global.b64 %0,[%1];" : "=l"(v) : "l"(p)); return v;
}
__device__ __forceinline__ void st_rlx_u64(unsigned long long* p, unsigned long long v) {
    asm volatile("st.relaxed.gpu.global.b64 [%0],%1;" :: "l"(p), "l"(v) : "memory");
}
__device__ __forceinline__ void fence_gpu() {
    asm volatile("fence.acq_rel.gpu;" ::: "memory");
}
__device__ __forceinline__ void bar_named(int id, int cnt) {
    asm volatile("bar.sync %0, %1;" :: "r"(id), "r"(cnt) : "memory");
}

// HW tanh (sm_75+ MUFU.TANH). |err| ~2^-11 — restructure is exact, so any
// rel_err delta this round is attributable to this instruction alone.
__device__ __forceinline__ float tanha(float x) {
    float y; asm("tanh.approx.f32 %0,%1;" : "=f"(y) : "f"(x)); return y;
}
__device__ __forceinline__ float sigf(float x) {       // sig(x) = 0.5*tanh(x/2)+0.5
    return fmaf(0.5f, tanha(0.5f * x), 0.5f);
}
__device__ __forceinline__ float wredu(float v) {
#pragma unroll
    for (int o = 16; o; o >>= 1) v += __shfl_xor_sync(0xffffffffu, v, o);
    return v;
}

// ---------------------------------------------------------------------------
// Kernel 0: reset tags + GI counters (runs every graph replay)
// ---------------------------------------------------------------------------
__global__ void init_kernel() {
    int i = blockIdx.x * blockDim.x + threadIdx.x;
    if (i < 2 * 2 * HD) ((unsigned long long*)g_htag)[i] = 0ull;   // tag 0 never matches t>=1
    if (i < 128) g_cnt[i] = 0u;
}

// ---------------------------------------------------------------------------
// Fused kernel: 148 CTAs x 768 threads.
//   CTAs [0,128):  persistent GRU recurrence, split by sequence:
//                  seq = bx>>6, c = bx&63 owns h indices [8c, 8c+8).
//                  24 warps x 1 gate row each; weights register-resident
//                  (16 floats/lane). h all-gathered via tag-embedded 8-byte
//                  words, exactly one polled word per thread. No global barrier.
//   CTAs [128,148): 3 x 256-thread GEMM units each, producing GI row-tiles,
//                  then prefetch tail weights into L2.
// ---------------------------------------------------------------------------
__global__ void __launch_bounds__(768, 1)
fused_kernel(const int* __restrict__ xs, const int* __restrict__ ys,
             const float* __restrict__ emb,
             const float* __restrict__ Wih, const float* __restrict__ bih,
             const float* __restrict__ Whh, const float* __restrict__ bhh,
             const float* __restrict__ Wih2, const float* __restrict__ Whh2,
             const float* __restrict__ W1) {
    const int tid = threadIdx.x;

    if (blockIdx.x >= REC_CTAS) {
        // ================== GEMM producer ==================
        __shared__ __align__(16) float pool[3 * 2048];
        const int gidx = tid >> 8;            // 0..2
        const int tidl = tid & 255;
        const int barid = gidx + 1;           // named barriers 1..3
        float* As = pool + gidx * 2048;
        float* Bs = As + 1024;

        const int tr = (tidl >> 4) << 2;
        const int tc = (tidl & 15) << 2;
        const int lr = tidl >> 2;
        const int kv = (tidl & 3) << 2;

        const int unit = (blockIdx.x - REC_CTAS) * 3 + gidx;

        for (int T = unit; T < NTILES; T += NUNITS) {
            const int e  = T / 24;
            const int c  = T - e * 24;
            const int xy = e & 1;
            const int trow = (e >> 1) << 6;
            const int col0 = c << 6;

            const int tok = (xy ? ys : xs)[trow + lr];
            const float* arow = emb + (size_t)tok * HD;
            const float* brow = Wih + (size_t)(col0 + lr) * HD;

            float acc[4][4];
#pragma unroll
            for (int i = 0; i < 4; i++)
#pragma unroll
                for (int j = 0; j < 4; j++) acc[i][j] = 0.0f;

            for (int k0 = 0; k0 < HD; k0 += 16) {
                float4 a4 = *(const float4*)(arow + k0 + kv);
                float4 b4 = *(const float4*)(brow + k0 + kv);
                As[(kv + 0) * 64 + lr] = a4.x; As[(kv + 1) * 64 + lr] = a4.y;
                As[(kv + 2) * 64 + lr] = a4.z; As[(kv + 3) * 64 + lr] = a4.w;
                Bs[(kv + 0) * 64 + lr] = b4.x; Bs[(kv + 1) * 64 + lr] = b4.y;
                Bs[(kv + 2) * 64 + lr] = b4.z; Bs[(kv + 3) * 64 + lr] = b4.w;
                bar_named(barid, 256);
#pragma unroll
                for (int k = 0; k < 16; k++) {
                    float4 av = *(const float4*)&As[k * 64 + tr];
                    float4 bv = *(const float4*)&Bs[k * 64 + tc];
                    acc[0][0] = fmaf(av.x, bv.x, acc[0][0]);
                    acc[0][1] = fmaf(av.x, bv.y, acc[0][1]);
                    acc[0][2] = fmaf(av.x, bv.z, acc[0][2]);
                    acc[0][3] = fmaf(av.x, bv.w, acc[0][3]);
                    acc[1][0] = fmaf(av.y, bv.x, acc[1][0]);
                    acc[1][1] = fmaf(av.y, bv.y, acc[1][1]);
                    acc[1][2] = fmaf(av.y, bv.z, acc[1][2]);
                    acc[1][3] = fmaf(av.y, bv.w, acc[1][3]);
                    acc[2][0] = fmaf(av.z, bv.x, acc[2][0]);
                    acc[2][1] = fmaf(av.z, bv.y, acc[2][1]);
                    acc[2][2] = fmaf(av.z, bv.z, acc[2][2]);
                    acc[2][3] = fmaf(av.z, bv.w, acc[2][3]);
                    acc[3][0] = fmaf(av.w, bv.x, acc[3][0]);
                    acc[3][1] = fmaf(av.w, bv.y, acc[3][1]);
                    acc[3][2] = fmaf(av.w, bv.z, acc[3][2]);
                    acc[3][3] = fmaf(av.w, bv.w, acc[3][3]);
                }
                bar_named(barid, 256);
            }

            float4 bias = *(const float4*)(bih + col0 + tc);
#pragma unroll
            for (int ii = 0; ii < 4; ii++) {
                float4 v;
                v.x = acc[ii][0] + bias.x;
                v.y = acc[ii][1] + bias.y;
                v.z = acc[ii][2] + bias.z;
                v.w = acc[ii][3] + bias.w;
                *(float4*)&g_GI[xy][trow + tr + ii][col0 + tc] = v;
            }
            bar_named(barid, 256);
            if (tidl == 0) {
                fence_gpu();
                red_rel_add(&g_cnt[e], 1u);
            }
        }

        // ---- warm L2 with tail weights (tails would otherwise be DRAM-bound)
        {
            const int nthr = GEMM_CTAS * 768;
            const int gt = (blockIdx.x - REC_CTAS) * 768 + tid;
            float s = 0.0f;
            const int n4 = (G3 * HD) / 4;
            for (int i = gt; i < n4; i += nthr) {
                float4 a = __ldcg((const float4*)Wih2 + i);
                float4 b = __ldcg((const float4*)Whh2 + i);
                s += a.x + a.w + b.x + b.w;
            }
            const int m4 = (128 * HD) / 4;
            for (int i = gt; i < m4; i += nthr) {
                float4 a = __ldcg((const float4*)W1 + i);
                s += a.x + a.w;
            }
            if (s == 1.2345678e38f) g_sink = s;    // never true; defeats DCE
        }
        return;
    }

    // ================== GRU recurrence (one sequence per CTA group) =========
    const int seq = blockIdx.x >> 6;          // 0 = x, 1 = y
    const int c   = blockIdx.x & 63;          // owns h indices [8c, 8c+8)
    const int w    = tid >> 5;                // 24 warps, 1 gate row each
    const int lane = tid & 31;

    __shared__ float sm_h[HD];
    __shared__ float sm_gh[24];

    const int g = w >> 3;                     // gate 0..2
    const int q = w & 7;                      // local h idx 0..7
    const int grow = (g << 9) + (c << 3) + q; // global gate row

    float wa[16];
#pragma unroll
    for (int j = 0; j < 16; j++)
        wa[j] = Whh[(size_t)grow * HD + lane + 32 * j];
    const float bh = bhh[grow];
    const int i8 = (c << 3) + tid;            // owned h index (tid < 8)

    for (int t = 0; t < SEQT; t++) {
        // ---- GI readiness (one counter for this seq, every 64 steps) ----
        if ((t & 63) == 0) {
            if (tid == 0) {
                const int e = ((t >> 6) << 1) + seq;
                while (ld_acq_u32(&g_cnt[e]) < 24u) { }
            }
            __syncthreads();
        }

        // ---- GI prefetch (latency hides under the h poll) ----
        float gr, gz, gn;
        if (tid < 8) {
            const float* GI = &g_GI[seq][t][0];
            gr = GI[i8]; gz = GI[512 + i8]; gn = GI[1024 + i8];
        }

        // ---- stage h: exactly one tag-embedded word per thread ----
        if (tid < HD) {
            float hv;
            if (t == 0) {
                hv = 0.0f;
            } else {
                const unsigned long long* p = &g_htag[t & 1][seq][tid];
                unsigned long long a = ld_rlx_u64(p);
                while ((unsigned)(a >> 32) != (unsigned)t) a = ld_rlx_u64(p);
                hv = __uint_as_float((unsigned)a);
            }
            sm_h[tid] = hv;
        }
        __syncthreads();                       // (A)

        // ---- 1 gate row per warp, register weights ----
        float a0 = 0.f;
#pragma unroll
        for (int j = 0; j < 16; j++)
            a0 = fmaf(wa[j], sm_h[lane + 32 * j], a0);
#pragma unroll
        for (int o = 16; o; o >>= 1)
            a0 += __shfl_xor_sync(0xffffffffu, a0, o);
        if (lane == 0) sm_gh[w] = a0 + bh;
        __syncthreads();                       // (B)

        // ---- gate + publish (tag carries the dependency; no fence) ----
        if (tid < 8) {
            float r = sigf(gr + sm_gh[tid]);
            float z = sigf(gz + sm_gh[8 + tid]);
            float n = tanha(gn + r * sm_gh[16 + tid]);
            float hn = n + z * (sm_h[i8] - n);
            st_rlx_u64(&g_htag[(t + 1) & 1][seq][i8],
                       (((unsigned long long)(unsigned)(t + 1)) << 32) |
                       (unsigned long long)__float_as_uint(hn));
        }
        // Safety (re-verified for 8-wide ownership):
        //  - sm_h(t) reads at dot complete before bar(B); overwrites happen
        //    only after the full loop body, past bar(B).
        //  - sm_gh(t) reads by gating threads precede their arrival at bar(A)
        //    of t+1, which gates any sm_gh rewrite.
        //  - sm_h[i8] read at gating is self-owned: its t+1 tag is published
        //    only by the reading thread itself.
    }
}

// ---------------------------------------------------------------------------
// Tail A: sentence-GRU step 1 (input hidden_x, h_prev = 0). 128 CTAs x 128.
// ---------------------------------------------------------------------------
__global__ void __launch_bounds__(128) tailA(const float* __restrict__ Wih2,
                                             const float* __restrict__ bih2,
                                             const float* __restrict__ bhh2) {
    __shared__ float sx[HD];
    const int tid = threadIdx.x, w = tid >> 5, lane = tid & 31;
    for (int i = tid; i < HD; i += 128)
        sx[i] = __uint_as_float((unsigned)g_htag[0][0][i]);
    __syncthreads();

    const int i = blockIdx.x * 4 + w;
    float ar = 0.f, az = 0.f, an = 0.f;
    for (int k = 0; k < 16; k++) {
        int j = lane + 32 * k;
        float h = sx[j];
        ar = fmaf(Wih2[(size_t)i * HD + j], h, ar);
        az = fmaf(Wih2[(size_t)(512 + i) * HD + j], h, az);
        an = fmaf(Wih2[(size_t)(1024 + i) * HD + j], h, an);
    }
    ar = wredu(ar); az = wredu(az); an = wredu(an);
    if (lane == 0) {
        float r = sigf(ar + bih2[i] + bhh2[i]);
        float z = sigf(az + bih2[512 + i] + bhh2[512 + i]);
        float n = tanha(an + bih2[1024 + i] + r * bhh2[1024 + i]);
        g_h1[i] = (1.0f - z) * n;
    }
}

// ---------------------------------------------------------------------------
// Tail B: sentence-GRU step 2 (input hidden_y, h_prev = h1). 128 CTAs x 128.
// ---------------------------------------------------------------------------
__global__ void __launch_bounds__(128) tailB(const float* __restrict__ Wih2,
                                             const float* __restrict__ Whh2,
                                             const float* __restrict__ bih2,
                                             const float* __restrict__ bhh2) {
    __shared__ float sy[HD], s1[HD];
    const int tid = threadIdx.x, w = tid >> 5, lane = tid & 31;
    for (int i = tid; i < HD; i += 128) {
        sy[i] = __uint_as_float((unsigned)g_htag[0][1][i]);
        s1[i] = g_h1[i];
    }
    __syncthreads();

    const int i = blockIdx.x * 4 + w;
    float ir = 0.f, iz = 0.f, in_ = 0.f, hr = 0.f, hz = 0.f, hn_ = 0.f;
    for (int k = 0; k < 16; k++) {
        int j = lane + 32 * k;
        float hy = sy[j], h1 = s1[j];
        size_t r0 = (size_t)i * HD + j;
        size_t r1 = (size_t)(512 + i) * HD + j;
        size_t r2 = (size_t)(1024 + i) * HD + j;
        ir = fmaf(Wih2[r0], hy, ir);   hr = fmaf(Whh2[r0], h1, hr);
        iz = fmaf(Wih2[r1], hy, iz);   hz = fmaf(Whh2[r1], h1, hz);
        in_ = fmaf(Wih2[r2], hy, in_); hn_ = fmaf(Whh2[r2], h1, hn_);
    }
    ir = wredu(ir); iz = wredu(iz); in_ = wredu(in_);
    hr = wredu(hr); hz = wredu(hz); hn_ = wredu(hn_);
    if (lane == 0) {
        float r = sigf(ir + bih2[i] + hr + bhh2[i]);
        float z = sigf(iz + bih2[512 + i] + hz + bhh2[512 + i]);
        float n = tanha(in_ + bih2[1024 + i] + r * (hn_ + bhh2[1024 + i]));
        g_h2[i] = n + z * (s1[i] - n);
    }
}

// ---------------------------------------------------------------------------
// Tail C: MLP + log_softmax. 1 CTA x 1024.
// ---------------------------------------------------------------------------
__global__ void __launch_bounds__(1024) tailC(const float* __restrict__ W1,
                                              const float* __restrict__ b1,
                                              const float* __restrict__ W2,
                                              const float* __restrict__ b2,
                                              float* __restrict__ out) {
    __shared__ float s2[HD], m1[128];
    const int tid = threadIdx.x, w = tid >> 5, lane = tid & 31;
    if (tid < HD) s2[tid] = g_h2[tid];
    __syncthreads();

    const int r0 = w * 4;
    float acc[4] = {0.f, 0.f, 0.f, 0.f};
    for (int k = 0; k < 16; k++) {
        int j = lane + 32 * k;
        float h = s2[j];
#pragma unroll
        for (int q = 0; q < 4; q++)
            acc[q] = fmaf(W1[(size_t)(r0 + q) * HD + j], h, acc[q]);
    }
#pragma unroll
    for (int q = 0; q < 4; q++) acc[q] = wredu(acc[q]);
    if (lane == 0) {
#pragma unroll
        for (int q = 0; q < 4; q++)
            m1[r0 + q] = fmaxf(acc[q] + b1[r0 + q], 0.0f);
    }
    __syncthreads();

    if (w == 0) {
        float a0 = 0.f, a1 = 0.f;
        for (int k = 0; k < 4; k++) {
            int j = lane + 32 * k;
            a0 = fmaf(W2[j], m1[j], a0);
            a1 = fmaf(W2[128 + j], m1[j], a1);
        }
        a0 = wredu(a0);
        a1 = wredu(a1);
        if (lane == 0) {
            float v0 = fmaxf(a0 + b2[0], 0.0f);
            float v1 = fmaxf(a1 + b2[1], 0.0f);
            float m = fmaxf(v0, v1);
            float lse = m + logf(expf(v0 - m) + expf(v1 - m));
            out[0] = v0 - lse;
            out[1] = v1 - lse;
        }
    }
}

// ---------------------------------------------------------------------------
extern "C" void kernel_launch(void* const* d_in, const int* in_sizes, int n_in,
                              void* d_out, int out_size) {
    const int*   x    = (const int*)d_in[0];
    const int*   y    = (const int*)d_in[1];
    const float* emb  = (const float*)d_in[2];
    const float* Wih1 = (const float*)d_in[3];
    const float* Whh1 = (const float*)d_in[4];
    const float* bih1 = (const float*)d_in[5];
    const float* bhh1 = (const float*)d_in[6];
    const float* Wih2 = (const float*)d_in[7];
    const float* Whh2 = (const float*)d_in[8];
    const float* bih2 = (const float*)d_in[9];
    const float* bhh2 = (const float*)d_in[10];
    const float* W1   = (const float*)d_in[11];
    const float* b1   = (const float*)d_in[12];
    const float* W2   = (const float*)d_in[13];
    const float* b2   = (const float*)d_in[14];
    float* out = (float*)d_out;

    init_kernel<<<2, 1024>>>();
    fused_kernel<<<REC_CTAS + GEMM_CTAS, 768>>>(x, y, emb, Wih1, bih1, Whh1, bhh1,
                                                Wih2, Whh2, W1);
    tailA<<<128, 128>>>(Wih2, bih2, bhh2);
    tailB<<<128, 128>>>(Wih2, Whh2, bih2, bhh2);
    tailC<<<1, 1024>>>(W1, b1, W2, b2, out);
}